// round 14
// baseline (speedup 1.0000x reference)
#include <cuda_runtime.h>

// ---------------------------------------------------------------------------
// TypeGAT HICS, inverted formulation, v14 = v13 with HALF the scan LDG issue.
//
// k_scan is LSU-ISSUE-bound (4 LDG.128/thread x 4-cyc structural floor ≈ the
// whole kernel; DRAM ~1%). So: load ONLY src4+dst4 speculatively; fetch
// times[e]/etypes[e] scalar on the ~2.5% bitmap-hit path. Issue count halves.
//
//  k_scan : 148 x 512, one int4-group per thread, branch-free SMEM bitmap
//           fast-reject, SMEM hash on hits, fused 16B {key,type} pushes,
//           early PDL trigger.
//  k_agg  : PDL-launched, 1 block/entity, 128 threads: speculative loads,
//           warp shfl-rank exact top-k, fixed-trip unrolled gather.
//
// Key packing preserves lax.top_k ordering: time desc, edge index asc.
// ---------------------------------------------------------------------------

#define MAX_B       4096
#define CAP         64
#define MAX_NODES   (1 << 20)
#define MAXK        32
#define HASH_SLOTS  4096
#define HASH_MASK   (HASH_SLOTS - 1)
#define EMPTY       0xFFFFFFFFu
#define BM_WORDS    2048          // 8KB bitmap -> nodes < 65536 on fast path
#define SCAN_BLK    148
#define SCAN_THR    512

__device__ int        g_cnt[2 * MAX_B];                 // zero at load; k_agg restores
__device__ ulonglong2 g_cand_inc[(size_t)MAX_B * CAP];  // {key, type}
__device__ ulonglong2 g_cand_out[(size_t)MAX_B * CAP];

__device__ __forceinline__ unsigned int hash_node(unsigned int node) {
    return (node * 2654435761u) >> 20;   // top 12 bits -> [0, 4096)
}

// Orderable key: (monotone float bits << 32) | ~edge_index.
// Max key == (largest time, smallest index) — matches lax.top_k tie-break.
__device__ __forceinline__ unsigned long long pack_key(float t, unsigned int e) {
    unsigned int tb = __float_as_uint(t);
    tb = (tb & 0x80000000u) ? ~tb : (tb | 0x80000000u);
    return ((unsigned long long)tb << 32) | (unsigned long long)(~e);
}

__device__ __forceinline__ void probe_push(const unsigned int* s_tab, unsigned int node,
                                           unsigned long long key, int etype, int dir,
                                           ulonglong2* __restrict__ cand) {
    unsigned int h = hash_node(node), v;
    while ((v = s_tab[h]) != EMPTY) {
        if ((v >> 12) == node) {
            int b = (int)(v & 0xFFFu);
            int p = atomicAdd(&g_cnt[2 * b + dir], 1);
            if (p < CAP)
                cand[(size_t)b * CAP + p] =
                    make_ulonglong2(key, (unsigned long long)(unsigned int)etype);
        }
        h = (h + 1) & HASH_MASK;
    }
}

__device__ __forceinline__ bool probe_any(const unsigned int* s_tab, unsigned int node) {
    unsigned int h = hash_node(node), v;
    while ((v = s_tab[h]) != EMPTY) {
        if ((v >> 12) == node) return true;
        h = (h + 1) & HASH_MASK;
    }
    return false;
}

// ---------------------------------------------------------------------------
// Kernel 1: edge scan. Full chip; bitmap fast-reject; minimal LDG issue.
// ---------------------------------------------------------------------------
__global__ void __launch_bounds__(SCAN_THR, 1)
k_scan(const int* __restrict__ src, const int* __restrict__ dst,
       const int* __restrict__ etypes, const float* __restrict__ times, int E,
       const int* __restrict__ ent, int B, const int* __restrict__ nn_ptr) {
    __shared__ unsigned int s_tab[HASH_SLOTS];
    __shared__ unsigned int s_bm[BM_WORDS];

    int tid    = threadIdx.x;
    int gid    = blockIdx.x * SCAN_THR + tid;
    int stride = gridDim.x * SCAN_THR;
    int E4     = E >> 2;
    const int4* src4 = (const int4*)src;
    const int4* dst4 = (const int4*)dst;

    // ---- critical-path loads first (hash build gates the tests) ----
    int nn = nn_ptr[0];
    int my_node = (tid < B && tid < MAX_B) ? ent[tid] : -1;

    // ---- speculative src/dst only (2 LDG.128; times/types fetched on hit) --
    bool have = gid < E4;
    int li = have ? gid : 0;
    int4 d4 = dst4[li];
    int4 s4 = src4[li];

    // ---- clear tables (pure SMEM, overlaps loads above) ----
    for (int i = tid; i < HASH_SLOTS; i += SCAN_THR) s_tab[i] = EMPTY;
    for (int i = tid; i < BM_WORDS; i += SCAN_THR) s_bm[i] = 0u;
    __syncthreads();

    if (nn > MAX_NODES) nn = MAX_NODES;
    bool small = (nn <= BM_WORDS * 32);
    for (int b = tid; b < B && b < MAX_B; b += SCAN_THR) {
        int node = (b == tid) ? my_node : ent[b];
        if (node >= 0 && node < nn) {
            unsigned int val = ((unsigned int)node << 12) | (unsigned int)b;
            unsigned int h = hash_node((unsigned int)node);
            while (atomicCAS(&s_tab[h], EMPTY, val) != EMPTY) h = (h + 1) & HASH_MASK;
            if ((unsigned int)node < BM_WORDS * 32u)
                atomicOr(&s_bm[(unsigned int)node >> 5], 1u << (node & 31));
        }
    }
    __syncthreads();

    unsigned int unn = (unsigned int)nn;

    // ---- process groups ----
    for (int i = gid; ; i += stride) {
        if (have) {
            int e0 = i << 2;
#pragma unroll
            for (int j = 0; j < 4; ++j) {
                unsigned int d = (unsigned int)((j == 0) ? d4.x : (j == 1) ? d4.y : (j == 2) ? d4.z : d4.w);
                unsigned int s = (unsigned int)((j == 0) ? s4.x : (j == 1) ? s4.y : (j == 2) ? s4.z : s4.w);
                bool hd, hs;
                if (small) {
                    hd = (d < unn) && ((s_bm[d >> 5] >> (d & 31)) & 1u);
                    hs = (s < unn) && ((s_bm[s >> 5] >> (s & 31)) & 1u);
                } else {
                    hd = (d < unn) && (d < BM_WORDS * 32u
                           ? ((s_bm[d >> 5] >> (d & 31)) & 1u) : probe_any(s_tab, d));
                    hs = (s < unn) && (s < BM_WORDS * 32u
                           ? ((s_bm[s >> 5] >> (s & 31)) & 1u) : probe_any(s_tab, s));
                }
                if (hd | hs) {
                    int e = e0 + j;
                    // rare path (~2.5% of edges): both loads issue together
                    float t  = __ldg(&times[e]);
                    int   ty = __ldg(&etypes[e]);
                    unsigned long long key = pack_key(t, (unsigned int)e);
                    if (hd) probe_push(s_tab, d, key, ty, 0, g_cand_inc);
                    if (hs) probe_push(s_tab, s, key, ty, 1, g_cand_out);
                }
            }
        }
        int nx = i + stride;
        if (nx >= E4) break;
        d4 = dst4[nx]; s4 = src4[nx];
        have = true;
    }

    // tail (E not multiple of 4)
    for (int e = (E4 << 2) + gid; e < E; e += stride) {
        unsigned int d = (unsigned int)dst[e];
        unsigned int s = (unsigned int)src[e];
        bool hd = (d < unn) && (d < BM_WORDS * 32u
                    ? ((s_bm[d >> 5] >> (d & 31)) & 1u) : probe_any(s_tab, d));
        bool hs = (s < unn) && (s < BM_WORDS * 32u
                    ? ((s_bm[s >> 5] >> (s & 31)) & 1u) : probe_any(s_tab, s));
        if (hd | hs) {
            unsigned long long key = pack_key(times[e], (unsigned int)e);
            int ty = etypes[e];
            if (hd) probe_push(s_tab, d, key, ty, 0, g_cand_inc);
            if (hs) probe_push(s_tab, s, key, ty, 1, g_cand_out);
        }
    }

    // ---- early PDL trigger: this block's pushes are done & visible ----
    __syncthreads();
    __threadfence();
    cudaTriggerProgrammaticLaunchCompletion();
}

// Fallback exact top-`take` for n > 32: iterative warp-max.
__device__ __forceinline__ void warp_select_big(const ulonglong2* __restrict__ row,
                                                int n, int take,
                                                int* s_types, int off, int lane) {
    unsigned long long thresh = ~0ull;
    for (int r = 0; r < take; ++r) {
        unsigned long long bk = 0ull; int bt = 0;
        for (int i = lane; i < n && i < CAP; i += 32) {
            ulonglong2 c = row[i];
            if (c.x < thresh && c.x > bk) { bk = c.x; bt = (int)c.y; }
        }
#pragma unroll
        for (int o = 16; o; o >>= 1) {
            unsigned long long ok = __shfl_xor_sync(0xffffffffu, bk, o);
            int                ot = __shfl_xor_sync(0xffffffffu, bt, o);
            if (ok > bk) { bk = ok; bt = ot; }
        }
        if (lane == 0) s_types[off + r] = bt;
        thresh = bk;
    }
}

// ---------------------------------------------------------------------------
// Kernel 2: selection + masked mean. PDL-aware. One block per entity.
// ---------------------------------------------------------------------------
__global__ void __launch_bounds__(128)
k_agg(const float* __restrict__ qw, float* __restrict__ out, int B, int D,
      const int* __restrict__ k_ptr) {
    int b = blockIdx.x;

    __shared__ int s_types[MAXK];
    __shared__ int s_n;

    int tid = threadIdx.x, wid = tid >> 5, lane = tid & 31;

    // Prologue: harness inputs only (not written by k_scan).
    int k = k_ptr[0];
    if (k > MAXK) k = MAXK;
    if (k < 0)    k = 0;
    int kh = k >> 1;

    cudaGridDependencySynchronize();
    if (b >= B || b >= MAX_B) return;

    if (wid < 2) {
        const ulonglong2* row = (wid == 0) ? &g_cand_inc[(size_t)b * CAP]
                                           : &g_cand_out[(size_t)b * CAP];
        ulonglong2 c = row[lane];                 // speculative
        int2 cc = ((const int2*)g_cnt)[b];
        int cin = cc.x, cout = cc.y;

        int inc_take  = kh < cin ? kh : cin;
        int remaining = (inc_take > 0) ? (k - inc_take) : k;
        int out_take  = remaining < cout ? remaining : cout;

        int n_mine = (wid == 0) ? cin : cout;
        int take   = (wid == 0) ? inc_take : out_take;
        int off    = (wid == 0) ? 0 : inc_take;

        if (n_mine <= 32) {
            unsigned long long key = (lane < n_mine) ? c.x : 0ull;
            int rank = 0;
#pragma unroll
            for (int j = 0; j < 32; ++j) {
                unsigned long long o = __shfl_sync(0xffffffffu, key, j);
                rank += (o > key);
            }
            if (lane < n_mine && rank < take) s_types[off + rank] = (int)c.y;
        } else {
            warp_select_big(row, n_mine < CAP ? n_mine : CAP, take,
                            s_types, off, lane);
        }

        if (wid == 0 && lane == 0) {
            s_n = inc_take + out_take;
            ((int2*)g_cnt)[b] = make_int2(0, 0);   // restore invariant
        }
    }
    __syncthreads();

    int n = s_n;
    float denom = fmaxf((float)n, 1.0f);

    for (int d = tid; d < D; d += blockDim.x) {
        float sum = 0.0f;
#pragma unroll
        for (int i = 0; i < 16; ++i) {
            float v = (i < n) ? qw[(size_t)s_types[i] * D + d] : 0.0f;
            sum += v;
        }
        for (int i = 16; i < n; ++i)               // safety for n > 16
            sum += qw[(size_t)s_types[i] * D + d];
        out[(size_t)b * D + d] = sum / denom;
    }
}

// ---------------------------------------------------------------------------
// Host launcher (graph-capturable: launches only; PDL edge between them).
// Inputs: entity_index, edge_src, edge_dst, edge_types, edge_times,
//         query_weight, k, num_nodes.
// ---------------------------------------------------------------------------
extern "C" void kernel_launch(void* const* d_in, const int* in_sizes, int n_in,
                              void* d_out, int out_size) {
    const int*   ent = (const int*)d_in[0];
    const int*   src = (const int*)d_in[1];
    const int*   dst = (const int*)d_in[2];
    const int*   typ = (const int*)d_in[3];
    const float* tim = (const float*)d_in[4];
    const float* qw  = (const float*)d_in[5];
    const int*   kp  = (const int*)d_in[6];
    const int*   nnp = (const int*)d_in[7];

    int B = in_sizes[0];
    int E = in_sizes[1];
    int D = (B > 0) ? (out_size / B) : 0;

    k_scan<<<SCAN_BLK, SCAN_THR>>>(src, dst, typ, tim, E, ent, B, nnp);

    cudaLaunchAttribute attrs[1];
    attrs[0].id = cudaLaunchAttributeProgrammaticStreamSerialization;
    attrs[0].val.programmaticStreamSerializationAllowed = 1;
    cudaLaunchConfig_t cfg = {};
    cfg.gridDim  = dim3((unsigned)B, 1, 1);
    cfg.blockDim = dim3(128, 1, 1);
    cfg.dynamicSmemBytes = 0;
    cfg.stream = 0;
    cfg.attrs = attrs;
    cfg.numAttrs = 1;
    cudaLaunchKernelEx(&cfg, k_agg, qw, (float*)d_out, B, D, kp);
}

// round 15
// speedup vs baseline: 1.0496x; 1.0496x over previous
#include <cuda_runtime.h>

// ---------------------------------------------------------------------------
// TypeGAT HICS, inverted formulation, v15 = v13 scan + 2-entities/block agg.
//
//  k_scan : 148 x 512 (one block/SM, <=1 int4-group/thread). Critical-path
//           ent/nn loads first, speculative src/dst/type/time int4 loads,
//           branch-free SMEM bitmap fast-reject, SMEM hash on hits, fused
//           16B {key,type} candidate pushes, early PDL trigger.
//  k_agg  : PDL-launched, 256 blocks x 256 threads (2 entities per block —
//           halves the post-release CTA wave). Speculative candidate+counter
//           loads, warp shfl-rank exact top-k, fixed-trip unrolled gather.
//
// Key packing preserves lax.top_k ordering: time desc, edge index asc.
// ---------------------------------------------------------------------------

#define MAX_B       4096
#define CAP         64
#define MAX_NODES   (1 << 20)
#define MAXK        32
#define HASH_SLOTS  4096
#define HASH_MASK   (HASH_SLOTS - 1)
#define EMPTY       0xFFFFFFFFu
#define BM_WORDS    2048          // 8KB bitmap -> nodes < 65536 on fast path
#define SCAN_BLK    148
#define SCAN_THR    512

__device__ int        g_cnt[2 * MAX_B];                 // zero at load; k_agg restores
__device__ ulonglong2 g_cand_inc[(size_t)MAX_B * CAP];  // {key, type}
__device__ ulonglong2 g_cand_out[(size_t)MAX_B * CAP];

__device__ __forceinline__ unsigned int hash_node(unsigned int node) {
    return (node * 2654435761u) >> 20;   // top 12 bits -> [0, 4096)
}

// Orderable key: (monotone float bits << 32) | ~edge_index.
// Max key == (largest time, smallest index) — matches lax.top_k tie-break.
__device__ __forceinline__ unsigned long long pack_key(float t, unsigned int e) {
    unsigned int tb = __float_as_uint(t);
    tb = (tb & 0x80000000u) ? ~tb : (tb | 0x80000000u);
    return ((unsigned long long)tb << 32) | (unsigned long long)(~e);
}

__device__ __forceinline__ void probe_push(const unsigned int* s_tab, unsigned int node,
                                           unsigned long long key, int etype, int dir,
                                           ulonglong2* __restrict__ cand) {
    unsigned int h = hash_node(node), v;
    while ((v = s_tab[h]) != EMPTY) {
        if ((v >> 12) == node) {
            int b = (int)(v & 0xFFFu);
            int p = atomicAdd(&g_cnt[2 * b + dir], 1);
            if (p < CAP)
                cand[(size_t)b * CAP + p] =
                    make_ulonglong2(key, (unsigned long long)(unsigned int)etype);
        }
        h = (h + 1) & HASH_MASK;
    }
}

__device__ __forceinline__ bool probe_any(const unsigned int* s_tab, unsigned int node) {
    unsigned int h = hash_node(node), v;
    while ((v = s_tab[h]) != EMPTY) {
        if ((v >> 12) == node) return true;
        h = (h + 1) & HASH_MASK;
    }
    return false;
}

// ---------------------------------------------------------------------------
// Kernel 1: edge scan (byte-for-byte v13 behavior).
// ---------------------------------------------------------------------------
__global__ void __launch_bounds__(SCAN_THR, 1)
k_scan(const int* __restrict__ src, const int* __restrict__ dst,
       const int* __restrict__ etypes, const float* __restrict__ times, int E,
       const int* __restrict__ ent, int B, const int* __restrict__ nn_ptr) {
    __shared__ unsigned int s_tab[HASH_SLOTS];
    __shared__ unsigned int s_bm[BM_WORDS];

    int tid    = threadIdx.x;
    int gid    = blockIdx.x * SCAN_THR + tid;
    int stride = gridDim.x * SCAN_THR;
    int E4     = E >> 2;
    const int4*   src4 = (const int4*)src;
    const int4*   dst4 = (const int4*)dst;
    const int4*   typ4 = (const int4*)etypes;
    const float4* tim4 = (const float4*)times;

    // ---- critical-path loads FIRST (hash build gates the tests) ----
    int nn = nn_ptr[0];
    int my_node = (tid < B && tid < MAX_B) ? ent[tid] : -1;

    // ---- speculative edge loads (consumed only after __syncthreads) ----
    bool have = gid < E4;
    int li = have ? gid : 0;
    int4   d4 = dst4[li];
    int4   s4 = src4[li];
    int4   y4 = typ4[li];
    float4 t4 = tim4[li];

    // ---- clear tables (pure SMEM, overlaps all loads above) ----
    for (int i = tid; i < HASH_SLOTS; i += SCAN_THR) s_tab[i] = EMPTY;
    for (int i = tid; i < BM_WORDS; i += SCAN_THR) s_bm[i] = 0u;
    __syncthreads();

    if (nn > MAX_NODES) nn = MAX_NODES;
    bool small = (nn <= BM_WORDS * 32);
    for (int b = tid; b < B && b < MAX_B; b += SCAN_THR) {
        int node = (b == tid) ? my_node : ent[b];
        if (node >= 0 && node < nn) {
            unsigned int val = ((unsigned int)node << 12) | (unsigned int)b;
            unsigned int h = hash_node((unsigned int)node);
            while (atomicCAS(&s_tab[h], EMPTY, val) != EMPTY) h = (h + 1) & HASH_MASK;
            if ((unsigned int)node < BM_WORDS * 32u)
                atomicOr(&s_bm[(unsigned int)node >> 5], 1u << (node & 31));
        }
    }
    __syncthreads();

    unsigned int unn = (unsigned int)nn;

    for (int i = gid; ; i += stride) {
        if (have) {
            int e0 = i << 2;
#pragma unroll
            for (int j = 0; j < 4; ++j) {
                unsigned int d = (unsigned int)((j == 0) ? d4.x : (j == 1) ? d4.y : (j == 2) ? d4.z : d4.w);
                unsigned int s = (unsigned int)((j == 0) ? s4.x : (j == 1) ? s4.y : (j == 2) ? s4.z : s4.w);
                bool hd, hs;
                if (small) {
                    hd = (d < unn) && ((s_bm[d >> 5] >> (d & 31)) & 1u);
                    hs = (s < unn) && ((s_bm[s >> 5] >> (s & 31)) & 1u);
                } else {
                    hd = (d < unn) && (d < BM_WORDS * 32u
                           ? ((s_bm[d >> 5] >> (d & 31)) & 1u) : probe_any(s_tab, d));
                    hs = (s < unn) && (s < BM_WORDS * 32u
                           ? ((s_bm[s >> 5] >> (s & 31)) & 1u) : probe_any(s_tab, s));
                }
                if (hd | hs) {
                    float t  = (j == 0) ? t4.x : (j == 1) ? t4.y : (j == 2) ? t4.z : t4.w;
                    int   ty = (j == 0) ? y4.x : (j == 1) ? y4.y : (j == 2) ? y4.z : y4.w;
                    unsigned long long key = pack_key(t, (unsigned int)(e0 + j));
                    if (hd) probe_push(s_tab, d, key, ty, 0, g_cand_inc);
                    if (hs) probe_push(s_tab, s, key, ty, 1, g_cand_out);
                }
            }
        }
        int nx = i + stride;
        if (nx >= E4) break;
        d4 = dst4[nx]; s4 = src4[nx]; y4 = typ4[nx]; t4 = tim4[nx];
        have = true;
    }

    for (int e = (E4 << 2) + gid; e < E; e += stride) {
        unsigned int d = (unsigned int)dst[e];
        unsigned int s = (unsigned int)src[e];
        bool hd = (d < unn) && (d < BM_WORDS * 32u
                    ? ((s_bm[d >> 5] >> (d & 31)) & 1u) : probe_any(s_tab, d));
        bool hs = (s < unn) && (s < BM_WORDS * 32u
                    ? ((s_bm[s >> 5] >> (s & 31)) & 1u) : probe_any(s_tab, s));
        if (hd | hs) {
            unsigned long long key = pack_key(times[e], (unsigned int)e);
            int ty = etypes[e];
            if (hd) probe_push(s_tab, d, key, ty, 0, g_cand_inc);
            if (hs) probe_push(s_tab, s, key, ty, 1, g_cand_out);
        }
    }

    // ---- early PDL trigger: this block's pushes done & visible ----
    __syncthreads();
    __threadfence();
    cudaTriggerProgrammaticLaunchCompletion();
}

// Fallback exact top-`take` for n > 32: iterative warp-max.
__device__ __forceinline__ void warp_select_big(const ulonglong2* __restrict__ row,
                                                int n, int take,
                                                int* s_types, int off, int lane) {
    unsigned long long thresh = ~0ull;
    for (int r = 0; r < take; ++r) {
        unsigned long long bk = 0ull; int bt = 0;
        for (int i = lane; i < n && i < CAP; i += 32) {
            ulonglong2 c = row[i];
            if (c.x < thresh && c.x > bk) { bk = c.x; bt = (int)c.y; }
        }
#pragma unroll
        for (int o = 16; o; o >>= 1) {
            unsigned long long ok = __shfl_xor_sync(0xffffffffu, bk, o);
            int                ot = __shfl_xor_sync(0xffffffffu, bt, o);
            if (ok > bk) { bk = ok; bt = ot; }
        }
        if (lane == 0) s_types[off + r] = bt;
        thresh = bk;
    }
}

// ---------------------------------------------------------------------------
// Kernel 2: selection + masked mean. PDL-aware. 2 entities per block.
// ---------------------------------------------------------------------------
__global__ void __launch_bounds__(256)
k_agg(const float* __restrict__ qw, float* __restrict__ out, int B, int D,
      const int* __restrict__ k_ptr) {
    __shared__ int s_types[2][MAXK];
    __shared__ int s_n[2];

    int tid  = threadIdx.x;
    int grp  = tid >> 7;            // 0 or 1
    int gtid = tid & 127;
    int wid  = gtid >> 5;
    int lane = tid & 31;
    int b    = blockIdx.x * 2 + grp;

    // Prologue: harness inputs only (not written by k_scan).
    int k = k_ptr[0];
    if (k > MAXK) k = MAXK;
    if (k < 0)    k = 0;
    int kh = k >> 1;

    cudaGridDependencySynchronize();

    bool active = (b < B && b < MAX_B);

    if (active && wid < 2) {
        const ulonglong2* row = (wid == 0) ? &g_cand_inc[(size_t)b * CAP]
                                           : &g_cand_out[(size_t)b * CAP];
        ulonglong2 c = row[lane];                 // speculative
        int2 cc = ((const int2*)g_cnt)[b];
        int cin = cc.x, cout = cc.y;

        int inc_take  = kh < cin ? kh : cin;
        int remaining = (inc_take > 0) ? (k - inc_take) : k;
        int out_take  = remaining < cout ? remaining : cout;

        int n_mine = (wid == 0) ? cin : cout;
        int take   = (wid == 0) ? inc_take : out_take;
        int off    = (wid == 0) ? 0 : inc_take;

        if (n_mine <= 32) {
            unsigned long long key = (lane < n_mine) ? c.x : 0ull;
            int rank = 0;
#pragma unroll
            for (int j = 0; j < 32; ++j) {
                unsigned long long o = __shfl_sync(0xffffffffu, key, j);
                rank += (o > key);
            }
            if (lane < n_mine && rank < take) s_types[grp][off + rank] = (int)c.y;
        } else {
            warp_select_big(row, n_mine < CAP ? n_mine : CAP, take,
                            s_types[grp], off, lane);
        }

        if (wid == 0 && lane == 0) {
            s_n[grp] = inc_take + out_take;
            ((int2*)g_cnt)[b] = make_int2(0, 0);   // restore invariant
        }
    }
    __syncthreads();

    if (!active) return;

    int n = s_n[grp];
    float denom = fmaxf((float)n, 1.0f);

    for (int d = gtid; d < D; d += 128) {
        float sum = 0.0f;
#pragma unroll
        for (int i = 0; i < 16; ++i) {
            float v = (i < n) ? qw[(size_t)s_types[grp][i] * D + d] : 0.0f;
            sum += v;
        }
        for (int i = 16; i < n; ++i)               // safety for n > 16
            sum += qw[(size_t)s_types[grp][i] * D + d];
        out[(size_t)b * D + d] = sum / denom;
    }
}

// ---------------------------------------------------------------------------
// Host launcher (graph-capturable: launches only; PDL edge between them).
// Inputs: entity_index, edge_src, edge_dst, edge_types, edge_times,
//         query_weight, k, num_nodes.
// ---------------------------------------------------------------------------
extern "C" void kernel_launch(void* const* d_in, const int* in_sizes, int n_in,
                              void* d_out, int out_size) {
    const int*   ent = (const int*)d_in[0];
    const int*   src = (const int*)d_in[1];
    const int*   dst = (const int*)d_in[2];
    const int*   typ = (const int*)d_in[3];
    const float* tim = (const float*)d_in[4];
    const float* qw  = (const float*)d_in[5];
    const int*   kp  = (const int*)d_in[6];
    const int*   nnp = (const int*)d_in[7];

    int B = in_sizes[0];
    int E = in_sizes[1];
    int D = (B > 0) ? (out_size / B) : 0;

    k_scan<<<SCAN_BLK, SCAN_THR>>>(src, dst, typ, tim, E, ent, B, nnp);

    cudaLaunchAttribute attrs[1];
    attrs[0].id = cudaLaunchAttributeProgrammaticStreamSerialization;
    attrs[0].val.programmaticStreamSerializationAllowed = 1;
    cudaLaunchConfig_t cfg = {};
    cfg.gridDim  = dim3((unsigned)((B + 1) / 2), 1, 1);
    cfg.blockDim = dim3(256, 1, 1);
    cfg.dynamicSmemBytes = 0;
    cfg.stream = 0;
    cfg.attrs = attrs;
    cfg.numAttrs = 1;
    cudaLaunchKernelEx(&cfg, k_agg, qw, (float*)d_out, B, D, kp);
}

// round 16
// speedup vs baseline: 1.0518x; 1.0022x over previous
#include <cuda_runtime.h>

// ---------------------------------------------------------------------------
// TypeGAT HICS, inverted formulation, v16 = v15 with 4-entities/block agg
// (128 CTAs = one per SM = minimal post-PDL-release wave; the CTA-count
// lever produced R15's win, this is its last step).
//
//  k_scan : 148 x 512 (one block/SM). Critical-path ent/nn loads first,
//           speculative src/dst/type/time int4 loads, branch-free SMEM
//           bitmap fast-reject, SMEM hash on hits, fused 16B {key,type}
//           pushes, early PDL trigger.
//  k_agg  : PDL-launched, 128 blocks x 512 threads (4 entities per block).
//           Speculative candidate+counter loads, warp shfl-rank exact top-k,
//           fixed-trip unrolled gather. Counters restored to zero.
//
// Key packing preserves lax.top_k ordering: time desc, edge index asc.
// ---------------------------------------------------------------------------

#define MAX_B       4096
#define CAP         64
#define MAX_NODES   (1 << 20)
#define MAXK        32
#define HASH_SLOTS  4096
#define HASH_MASK   (HASH_SLOTS - 1)
#define EMPTY       0xFFFFFFFFu
#define BM_WORDS    2048          // 8KB bitmap -> nodes < 65536 on fast path
#define SCAN_BLK    148
#define SCAN_THR    512

__device__ int        g_cnt[2 * MAX_B];                 // zero at load; k_agg restores
__device__ ulonglong2 g_cand_inc[(size_t)MAX_B * CAP];  // {key, type}
__device__ ulonglong2 g_cand_out[(size_t)MAX_B * CAP];

__device__ __forceinline__ unsigned int hash_node(unsigned int node) {
    return (node * 2654435761u) >> 20;   // top 12 bits -> [0, 4096)
}

// Orderable key: (monotone float bits << 32) | ~edge_index.
// Max key == (largest time, smallest index) — matches lax.top_k tie-break.
__device__ __forceinline__ unsigned long long pack_key(float t, unsigned int e) {
    unsigned int tb = __float_as_uint(t);
    tb = (tb & 0x80000000u) ? ~tb : (tb | 0x80000000u);
    return ((unsigned long long)tb << 32) | (unsigned long long)(~e);
}

__device__ __forceinline__ void probe_push(const unsigned int* s_tab, unsigned int node,
                                           unsigned long long key, int etype, int dir,
                                           ulonglong2* __restrict__ cand) {
    unsigned int h = hash_node(node), v;
    while ((v = s_tab[h]) != EMPTY) {
        if ((v >> 12) == node) {
            int b = (int)(v & 0xFFFu);
            int p = atomicAdd(&g_cnt[2 * b + dir], 1);
            if (p < CAP)
                cand[(size_t)b * CAP + p] =
                    make_ulonglong2(key, (unsigned long long)(unsigned int)etype);
        }
        h = (h + 1) & HASH_MASK;
    }
}

__device__ __forceinline__ bool probe_any(const unsigned int* s_tab, unsigned int node) {
    unsigned int h = hash_node(node), v;
    while ((v = s_tab[h]) != EMPTY) {
        if ((v >> 12) == node) return true;
        h = (h + 1) & HASH_MASK;
    }
    return false;
}

// ---------------------------------------------------------------------------
// Kernel 1: edge scan (byte-for-byte v13/v15 behavior).
// ---------------------------------------------------------------------------
__global__ void __launch_bounds__(SCAN_THR, 1)
k_scan(const int* __restrict__ src, const int* __restrict__ dst,
       const int* __restrict__ etypes, const float* __restrict__ times, int E,
       const int* __restrict__ ent, int B, const int* __restrict__ nn_ptr) {
    __shared__ unsigned int s_tab[HASH_SLOTS];
    __shared__ unsigned int s_bm[BM_WORDS];

    int tid    = threadIdx.x;
    int gid    = blockIdx.x * SCAN_THR + tid;
    int stride = gridDim.x * SCAN_THR;
    int E4     = E >> 2;
    const int4*   src4 = (const int4*)src;
    const int4*   dst4 = (const int4*)dst;
    const int4*   typ4 = (const int4*)etypes;
    const float4* tim4 = (const float4*)times;

    // ---- critical-path loads FIRST (hash build gates the tests) ----
    int nn = nn_ptr[0];
    int my_node = (tid < B && tid < MAX_B) ? ent[tid] : -1;

    // ---- speculative edge loads (consumed only after __syncthreads) ----
    bool have = gid < E4;
    int li = have ? gid : 0;
    int4   d4 = dst4[li];
    int4   s4 = src4[li];
    int4   y4 = typ4[li];
    float4 t4 = tim4[li];

    // ---- clear tables (pure SMEM, overlaps all loads above) ----
    for (int i = tid; i < HASH_SLOTS; i += SCAN_THR) s_tab[i] = EMPTY;
    for (int i = tid; i < BM_WORDS; i += SCAN_THR) s_bm[i] = 0u;
    __syncthreads();

    if (nn > MAX_NODES) nn = MAX_NODES;
    bool small = (nn <= BM_WORDS * 32);
    for (int b = tid; b < B && b < MAX_B; b += SCAN_THR) {
        int node = (b == tid) ? my_node : ent[b];
        if (node >= 0 && node < nn) {
            unsigned int val = ((unsigned int)node << 12) | (unsigned int)b;
            unsigned int h = hash_node((unsigned int)node);
            while (atomicCAS(&s_tab[h], EMPTY, val) != EMPTY) h = (h + 1) & HASH_MASK;
            if ((unsigned int)node < BM_WORDS * 32u)
                atomicOr(&s_bm[(unsigned int)node >> 5], 1u << (node & 31));
        }
    }
    __syncthreads();

    unsigned int unn = (unsigned int)nn;

    for (int i = gid; ; i += stride) {
        if (have) {
            int e0 = i << 2;
#pragma unroll
            for (int j = 0; j < 4; ++j) {
                unsigned int d = (unsigned int)((j == 0) ? d4.x : (j == 1) ? d4.y : (j == 2) ? d4.z : d4.w);
                unsigned int s = (unsigned int)((j == 0) ? s4.x : (j == 1) ? s4.y : (j == 2) ? s4.z : s4.w);
                bool hd, hs;
                if (small) {
                    hd = (d < unn) && ((s_bm[d >> 5] >> (d & 31)) & 1u);
                    hs = (s < unn) && ((s_bm[s >> 5] >> (s & 31)) & 1u);
                } else {
                    hd = (d < unn) && (d < BM_WORDS * 32u
                           ? ((s_bm[d >> 5] >> (d & 31)) & 1u) : probe_any(s_tab, d));
                    hs = (s < unn) && (s < BM_WORDS * 32u
                           ? ((s_bm[s >> 5] >> (s & 31)) & 1u) : probe_any(s_tab, s));
                }
                if (hd | hs) {
                    float t  = (j == 0) ? t4.x : (j == 1) ? t4.y : (j == 2) ? t4.z : t4.w;
                    int   ty = (j == 0) ? y4.x : (j == 1) ? y4.y : (j == 2) ? y4.z : y4.w;
                    unsigned long long key = pack_key(t, (unsigned int)(e0 + j));
                    if (hd) probe_push(s_tab, d, key, ty, 0, g_cand_inc);
                    if (hs) probe_push(s_tab, s, key, ty, 1, g_cand_out);
                }
            }
        }
        int nx = i + stride;
        if (nx >= E4) break;
        d4 = dst4[nx]; s4 = src4[nx]; y4 = typ4[nx]; t4 = tim4[nx];
        have = true;
    }

    for (int e = (E4 << 2) + gid; e < E; e += stride) {
        unsigned int d = (unsigned int)dst[e];
        unsigned int s = (unsigned int)src[e];
        bool hd = (d < unn) && (d < BM_WORDS * 32u
                    ? ((s_bm[d >> 5] >> (d & 31)) & 1u) : probe_any(s_tab, d));
        bool hs = (s < unn) && (s < BM_WORDS * 32u
                    ? ((s_bm[s >> 5] >> (s & 31)) & 1u) : probe_any(s_tab, s));
        if (hd | hs) {
            unsigned long long key = pack_key(times[e], (unsigned int)e);
            int ty = etypes[e];
            if (hd) probe_push(s_tab, d, key, ty, 0, g_cand_inc);
            if (hs) probe_push(s_tab, s, key, ty, 1, g_cand_out);
        }
    }

    // ---- early PDL trigger: this block's pushes done & visible ----
    __syncthreads();
    __threadfence();
    cudaTriggerProgrammaticLaunchCompletion();
}

// Fallback exact top-`take` for n > 32: iterative warp-max.
__device__ __forceinline__ void warp_select_big(const ulonglong2* __restrict__ row,
                                                int n, int take,
                                                int* s_types, int off, int lane) {
    unsigned long long thresh = ~0ull;
    for (int r = 0; r < take; ++r) {
        unsigned long long bk = 0ull; int bt = 0;
        for (int i = lane; i < n && i < CAP; i += 32) {
            ulonglong2 c = row[i];
            if (c.x < thresh && c.x > bk) { bk = c.x; bt = (int)c.y; }
        }
#pragma unroll
        for (int o = 16; o; o >>= 1) {
            unsigned long long ok = __shfl_xor_sync(0xffffffffu, bk, o);
            int                ot = __shfl_xor_sync(0xffffffffu, bt, o);
            if (ok > bk) { bk = ok; bt = ot; }
        }
        if (lane == 0) s_types[off + r] = bt;
        thresh = bk;
    }
}

// ---------------------------------------------------------------------------
// Kernel 2: selection + masked mean. PDL-aware. 4 entities per block.
// ---------------------------------------------------------------------------
__global__ void __launch_bounds__(512)
k_agg(const float* __restrict__ qw, float* __restrict__ out, int B, int D,
      const int* __restrict__ k_ptr) {
    __shared__ int s_types[4][MAXK];
    __shared__ int s_n[4];

    int tid  = threadIdx.x;
    int grp  = tid >> 7;            // 0..3
    int gtid = tid & 127;
    int wid  = gtid >> 5;
    int lane = tid & 31;
    int b    = blockIdx.x * 4 + grp;

    // Prologue: harness inputs only (not written by k_scan).
    int k = k_ptr[0];
    if (k > MAXK) k = MAXK;
    if (k < 0)    k = 0;
    int kh = k >> 1;

    cudaGridDependencySynchronize();

    bool active = (b < B && b < MAX_B);

    if (active && wid < 2) {
        const ulonglong2* row = (wid == 0) ? &g_cand_inc[(size_t)b * CAP]
                                           : &g_cand_out[(size_t)b * CAP];
        ulonglong2 c = row[lane];                 // speculative
        int2 cc = ((const int2*)g_cnt)[b];
        int cin = cc.x, cout = cc.y;

        int inc_take  = kh < cin ? kh : cin;
        int remaining = (inc_take > 0) ? (k - inc_take) : k;
        int out_take  = remaining < cout ? remaining : cout;

        int n_mine = (wid == 0) ? cin : cout;
        int take   = (wid == 0) ? inc_take : out_take;
        int off    = (wid == 0) ? 0 : inc_take;

        if (n_mine <= 32) {
            unsigned long long key = (lane < n_mine) ? c.x : 0ull;
            int rank = 0;
#pragma unroll
            for (int j = 0; j < 32; ++j) {
                unsigned long long o = __shfl_sync(0xffffffffu, key, j);
                rank += (o > key);
            }
            if (lane < n_mine && rank < take) s_types[grp][off + rank] = (int)c.y;
        } else {
            warp_select_big(row, n_mine < CAP ? n_mine : CAP, take,
                            s_types[grp], off, lane);
        }

        if (wid == 0 && lane == 0) {
            s_n[grp] = inc_take + out_take;
            ((int2*)g_cnt)[b] = make_int2(0, 0);   // restore invariant
        }
    }
    __syncthreads();

    if (!active) return;

    int n = s_n[grp];
    float denom = fmaxf((float)n, 1.0f);

    for (int d = gtid; d < D; d += 128) {
        float sum = 0.0f;
#pragma unroll
        for (int i = 0; i < 16; ++i) {
            float v = (i < n) ? qw[(size_t)s_types[grp][i] * D + d] : 0.0f;
            sum += v;
        }
        for (int i = 16; i < n; ++i)               // safety for n > 16
            sum += qw[(size_t)s_types[grp][i] * D + d];
        out[(size_t)b * D + d] = sum / denom;
    }
}

// ---------------------------------------------------------------------------
// Host launcher (graph-capturable: launches only; PDL edge between them).
// Inputs: entity_index, edge_src, edge_dst, edge_types, edge_times,
//         query_weight, k, num_nodes.
// ---------------------------------------------------------------------------
extern "C" void kernel_launch(void* const* d_in, const int* in_sizes, int n_in,
                              void* d_out, int out_size) {
    const int*   ent = (const int*)d_in[0];
    const int*   src = (const int*)d_in[1];
    const int*   dst = (const int*)d_in[2];
    const int*   typ = (const int*)d_in[3];
    const float* tim = (const float*)d_in[4];
    const float* qw  = (const float*)d_in[5];
    const int*   kp  = (const int*)d_in[6];
    const int*   nnp = (const int*)d_in[7];

    int B = in_sizes[0];
    int E = in_sizes[1];
    int D = (B > 0) ? (out_size / B) : 0;

    k_scan<<<SCAN_BLK, SCAN_THR>>>(src, dst, typ, tim, E, ent, B, nnp);

    cudaLaunchAttribute attrs[1];
    attrs[0].id = cudaLaunchAttributeProgrammaticStreamSerialization;
    attrs[0].val.programmaticStreamSerializationAllowed = 1;
    cudaLaunchConfig_t cfg = {};
    cfg.gridDim  = dim3((unsigned)((B + 3) / 4), 1, 1);
    cfg.blockDim = dim3(512, 1, 1);
    cfg.dynamicSmemBytes = 0;
    cfg.stream = 0;
    cfg.attrs = attrs;
    cfg.numAttrs = 1;
    cudaLaunchKernelEx(&cfg, k_agg, qw, (float*)d_out, B, D, kp);
}